// round 7
// baseline (speedup 1.0000x reference)
#include <cuda_runtime.h>
#include <math.h>
#include <stdint.h>

// ---------------- problem constants (static in reference) ----------------
#define NB 4
#define LQ 13294
#define LEN_IN 13294
#define CC 256
#define NROWS (NB * LQ)   // 53176
#define NFUSE 384         // 256 offset logits + 128 attn logits

__device__ __constant__ int c_H[4]     = {100, 50, 25, 13};
__device__ __constant__ int c_W[4]     = {100, 50, 25, 13};
__device__ __constant__ int c_start[4] = {0, 10000, 12500, 13125};

// ---------------- scratch (device globals, no allocation) ----------------
__device__ float g_value[NROWS * CC];     // value projection
__device__ float g_oa[NROWS * NFUSE];     // fused [off(256) | attn(128)] logits
__device__ float g_ms[NROWS * CC];        // sampled output
__device__ float g_Wf[CC * NFUSE];        // concatenated [W_off | W_attn]
__device__ float g_bf[NFUSE];             // concatenated [b_off | b_attn]

// ---------------- prep: concat weights/biases ----------------
__global__ void concat_wb(const float* __restrict__ W_off,
                          const float* __restrict__ W_attn,
                          const float* __restrict__ b_off,
                          const float* __restrict__ b_attn,
                          float* __restrict__ Wf, float* __restrict__ bf)
{
    int i = blockIdx.x * 256 + threadIdx.x;
    if (i < CC * NFUSE) {
        int k = i / NFUSE, c = i % NFUSE;
        Wf[i] = (c < 256) ? W_off[k * 256 + c] : W_attn[k * 128 + (c - 256)];
    }
    if (i < NFUSE) bf[i] = (i < 256) ? b_off[i] : b_attn[i - 256];
}

// ---------------- tf32 tensor-core GEMM, double-buffered smem -------------
#define BM 128
#define BN 128
#define BK 32
#define ASTRIDE 36
#define BSTRIDE 136
#define A_STAGE (BM * ASTRIDE)             // uint32 per A stage
#define B_STAGE (BK * BSTRIDE)             // uint32 per B stage
#define SMEM_BYTES ((2 * A_STAGE + 2 * B_STAGE) * 4)

__device__ __forceinline__ uint32_t f2tf32(float x) {
    uint32_t r;
    asm("cvt.rna.tf32.f32 %0, %1;" : "=r"(r) : "f"(x));
    return r;
}

__device__ __forceinline__ void mma_tf32(float* d, const uint32_t* a,
                                         uint32_t b0, uint32_t b1) {
    asm volatile(
        "mma.sync.aligned.m16n8k8.row.col.f32.tf32.tf32.f32 "
        "{%0,%1,%2,%3},{%4,%5,%6,%7},{%8,%9},{%0,%1,%2,%3};"
        : "+f"(d[0]), "+f"(d[1]), "+f"(d[2]), "+f"(d[3])
        : "r"(a[0]), "r"(a[1]), "r"(a[2]), "r"(a[3]), "r"(b0), "r"(b1));
}

__global__ __launch_bounds__(256, 2) void gemm_tf32_bias(
    const float* __restrict__ A, const float* __restrict__ B,
    const float* __restrict__ bias, float* __restrict__ Cmat,
    int Mrows, int Ncols)
{
    extern __shared__ uint32_t sm[];
    uint32_t* AsBase = sm;                      // [2][BM][ASTRIDE]
    uint32_t* BsBase = sm + 2 * A_STAGE;        // [2][BK][BSTRIDE]

    const int tid  = threadIdx.x;
    const int lane = tid & 31;
    const int wid  = tid >> 5;
    const int wm   = (wid & 3) * 32;
    const int wn   = (wid >> 2) * 64;
    const int row0 = blockIdx.y * BM;
    const int col0 = blockIdx.x * BN;

    const int r  = lane >> 2;
    const int c  = lane & 3;

    int a_m[4], a_ks[4], b_k[4], b_seg[4];
    bool a_ok[4];
    #pragma unroll
    for (int j = 0; j < 4; j++) {
        int idx = tid + 256 * j;
        a_m[j]  = idx >> 3;
        a_ks[j] = (idx & 7) << 2;
        a_ok[j] = (row0 + a_m[j]) < Mrows;
        b_k[j]  = idx >> 5;
        b_seg[j] = (idx & 31) << 2;
    }

    float acc[2][8][4];
    #pragma unroll
    for (int mt = 0; mt < 2; mt++)
        #pragma unroll
        for (int nt = 0; nt < 8; nt++)
            #pragma unroll
            for (int i = 0; i < 4; i++) acc[mt][nt][i] = 0.f;

    float4 ra[4], rb[4];

    // prologue: load tile 0 -> regs -> stage 0
    #pragma unroll
    for (int j = 0; j < 4; j++) {
        ra[j] = a_ok[j] ? *reinterpret_cast<const float4*>(
                    A + (size_t)(row0 + a_m[j]) * CC + a_ks[j])
                        : make_float4(0.f, 0.f, 0.f, 0.f);
        rb[j] = *reinterpret_cast<const float4*>(
                    B + (size_t)b_k[j] * Ncols + col0 + b_seg[j]);
    }
    #pragma unroll
    for (int j = 0; j < 4; j++) {
        uint4 u;
        u.x = f2tf32(ra[j].x); u.y = f2tf32(ra[j].y);
        u.z = f2tf32(ra[j].z); u.w = f2tf32(ra[j].w);
        *reinterpret_cast<uint4*>(AsBase + a_m[j] * ASTRIDE + a_ks[j]) = u;
        uint4 v;
        v.x = f2tf32(rb[j].x); v.y = f2tf32(rb[j].y);
        v.z = f2tf32(rb[j].z); v.w = f2tf32(rb[j].w);
        *reinterpret_cast<uint4*>(BsBase + b_k[j] * BSTRIDE + b_seg[j]) = v;
    }
    __syncthreads();

    #pragma unroll
    for (int kt = 0; kt < CC / BK; kt++) {
        const uint32_t* As = AsBase + (kt & 1) * A_STAGE;
        const uint32_t* Bs = BsBase + (kt & 1) * B_STAGE;

        // prefetch next tile -> regs (overlaps MMA below)
        if (kt < CC / BK - 1) {
            const int k0 = (kt + 1) * BK;
            #pragma unroll
            for (int j = 0; j < 4; j++) {
                ra[j] = a_ok[j] ? *reinterpret_cast<const float4*>(
                            A + (size_t)(row0 + a_m[j]) * CC + k0 + a_ks[j])
                                : make_float4(0.f, 0.f, 0.f, 0.f);
                rb[j] = *reinterpret_cast<const float4*>(
                            B + (size_t)(k0 + b_k[j]) * Ncols + col0 + b_seg[j]);
            }
        }

        // MMA on current stage
        #pragma unroll
        for (int ks = 0; ks < 4; ks++) {
            const int kk = ks * 8;
            uint32_t afr[2][4];
            #pragma unroll
            for (int mt = 0; mt < 2; mt++) {
                int mbase = wm + mt * 16 + r;
                afr[mt][0] = As[mbase * ASTRIDE + kk + c];
                afr[mt][1] = As[(mbase + 8) * ASTRIDE + kk + c];
                afr[mt][2] = As[mbase * ASTRIDE + kk + c + 4];
                afr[mt][3] = As[(mbase + 8) * ASTRIDE + kk + c + 4];
            }
            #pragma unroll
            for (int nt = 0; nt < 8; nt++) {
                int nbase = wn + nt * 8 + r;
                uint32_t b0 = Bs[(kk + c) * BSTRIDE + nbase];
                uint32_t b1 = Bs[(kk + c + 4) * BSTRIDE + nbase];
                mma_tf32(acc[0][nt], afr[0], b0, b1);
                mma_tf32(acc[1][nt], afr[1], b0, b1);
            }
        }

        // commit next tile -> other stage
        if (kt < CC / BK - 1) {
            uint32_t* Asw = AsBase + ((kt + 1) & 1) * A_STAGE;
            uint32_t* Bsw = BsBase + ((kt + 1) & 1) * B_STAGE;
            #pragma unroll
            for (int j = 0; j < 4; j++) {
                uint4 u;
                u.x = f2tf32(ra[j].x); u.y = f2tf32(ra[j].y);
                u.z = f2tf32(ra[j].z); u.w = f2tf32(ra[j].w);
                *reinterpret_cast<uint4*>(Asw + a_m[j] * ASTRIDE + a_ks[j]) = u;
                uint4 v;
                v.x = f2tf32(rb[j].x); v.y = f2tf32(rb[j].y);
                v.z = f2tf32(rb[j].z); v.w = f2tf32(rb[j].w);
                *reinterpret_cast<uint4*>(Bsw + b_k[j] * BSTRIDE + b_seg[j]) = v;
            }
        }
        __syncthreads();
    }

    const int c2 = c * 2;
    #pragma unroll
    for (int mt = 0; mt < 2; mt++) {
        int row = row0 + wm + mt * 16 + r;
        #pragma unroll
        for (int nt = 0; nt < 8; nt++) {
            int col = col0 + wn + nt * 8 + c2;
            float b0 = __ldg(bias + col);
            float b1 = __ldg(bias + col + 1);
            if (row < Mrows) {
                float2 v = make_float2(acc[mt][nt][0] + b0, acc[mt][nt][1] + b1);
                *reinterpret_cast<float2*>(Cmat + (size_t)row * Ncols + col) = v;
            }
            if (row + 8 < Mrows) {
                float2 v = make_float2(acc[mt][nt][2] + b0, acc[mt][nt][3] + b1);
                *reinterpret_cast<float2*>(Cmat + (size_t)(row + 8) * Ncols + col) = v;
            }
        }
    }
}

// ---------------- sampling: one warp per (n, q, m) ----------------
__global__ __launch_bounds__(256) void msda_sample(const float* __restrict__ refpts)
{
    __shared__ float2 s_aw[8][64];      // per warp: 64 (weight, f4-offset) pairs

    const int nq = blockIdx.x;           // n*LQ + q
    const int m = threadIdx.x >> 5;      // head
    const int lane = threadIdx.x & 31;
    const int n = nq / LQ;

    {
        const int p = lane & 15;
        const int l = p >> 2;
        const int half = lane >> 4;      // dy

        float logit = g_oa[(size_t)nq * NFUSE + 256 + m * 16 + p];
        float mx = logit;
        #pragma unroll
        for (int o = 8; o >= 1; o >>= 1)
            mx = fmaxf(mx, __shfl_xor_sync(0xffffffffu, mx, o, 16));
        float e = __expf(logit - mx);
        float s = e;
        #pragma unroll
        for (int o = 8; o >= 1; o >>= 1)
            s += __shfl_xor_sync(0xffffffffu, s, o, 16);
        float prob = e / s;

        float2 offv = *reinterpret_cast<const float2*>(
            g_oa + (size_t)nq * NFUSE + m * 32 + 2 * p);
        float2 refv = *reinterpret_cast<const float2*>(
            refpts + (size_t)nq * 8 + 2 * l);

        const int Wi = c_W[l], Hi = c_H[l];
        const float Wf = (float)Wi, Hf = (float)Hi;

        float x = fmaf(refv.x, Wf, offv.x) - 0.5f;
        float y = fmaf(refv.y, Hf, offv.y) - 0.5f;
        float x0f = floorf(x), y0f = floorf(y);
        float wx = x - x0f, wy = y - y0f;
        int x0 = (int)x0f, y0 = (int)y0f;
        int x1 = x0 + 1;
        int yi = y0 + half;

        float vx0 = (x0 >= 0 && x0 < Wi) ? 1.f : 0.f;
        float vx1 = (x1 >= 0 && x1 < Wi) ? 1.f : 0.f;
        float vy  = (yi >= 0 && yi < Hi) ? 1.f : 0.f;
        float wyv = half ? wy : (1.f - wy);

        int cx0 = min(max(x0, 0), Wi - 1);
        int cx1 = min(max(x1, 0), Wi - 1);
        int cyi = min(max(yi, 0), Hi - 1);

        int rbase = (c_start[l] + cyi * Wi) * 64;   // float4 units
        int o0 = rbase + cx0 * 64;
        int o1 = rbase + cx1 * 64;

        float pv = prob * wyv * vy;
        float w0 = (1.f - wx) * pv * vx0;
        float w1 = wx * pv * vx1;

        float4 st = make_float4(w0, __int_as_float(o0),
                                w1, __int_as_float(o1));
        *reinterpret_cast<float4*>(&s_aw[m][p * 4 + half * 2]) = st;
    }
    __syncwarp();

    const int g  = lane >> 3;
    const int lg = lane & 7;
    const float4* vbase = reinterpret_cast<const float4*>(
        g_value + (size_t)n * LEN_IN * CC + m * 32) + lg;

    float4 acc = make_float4(0.f, 0.f, 0.f, 0.f);
    #pragma unroll
    for (int i = 0; i < 16; i++) {
        float2 e = s_aw[m][i * 4 + g];
        float4 v = __ldg(vbase + __float_as_int(e.y));
        acc.x = fmaf(v.x, e.x, acc.x);
        acc.y = fmaf(v.y, e.x, acc.y);
        acc.z = fmaf(v.z, e.x, acc.z);
        acc.w = fmaf(v.w, e.x, acc.w);
    }

    #pragma unroll
    for (int o = 8; o <= 16; o <<= 1) {
        acc.x += __shfl_xor_sync(0xffffffffu, acc.x, o);
        acc.y += __shfl_xor_sync(0xffffffffu, acc.y, o);
        acc.z += __shfl_xor_sync(0xffffffffu, acc.z, o);
        acc.w += __shfl_xor_sync(0xffffffffu, acc.w, o);
    }

    if (lane < 8) {
        *reinterpret_cast<float4*>(
            g_ms + (size_t)nq * 256 + m * 32 + lg * 4) = acc;
    }
}

// ---------------- launch ----------------
extern "C" void kernel_launch(void* const* d_in, const int* in_sizes, int n_in,
                              void* d_out, int out_size)
{
    const float* query         = (const float*)d_in[0];
    const float* refpts        = (const float*)d_in[1];
    const float* input_flatten = (const float*)d_in[2];
    const float* Wv     = (const float*)d_in[5];
    const float* bv     = (const float*)d_in[6];
    const float* W_off  = (const float*)d_in[7];
    const float* b_off  = (const float*)d_in[8];
    const float* W_attn = (const float*)d_in[9];
    const float* b_attn = (const float*)d_in[10];
    const float* Wo     = (const float*)d_in[11];
    const float* bo     = (const float*)d_in[12];
    float* out = (float*)d_out;

    float *p_value, *p_oa, *p_ms, *p_Wf, *p_bf;
    cudaGetSymbolAddress((void**)&p_value, g_value);
    cudaGetSymbolAddress((void**)&p_oa,    g_oa);
    cudaGetSymbolAddress((void**)&p_ms,    g_ms);
    cudaGetSymbolAddress((void**)&p_Wf,    g_Wf);
    cudaGetSymbolAddress((void**)&p_bf,    g_bf);

    static int smem_set = 0;
    if (!smem_set) {
        cudaFuncSetAttribute(gemm_tf32_bias,
                             cudaFuncAttributeMaxDynamicSharedMemorySize,
                             SMEM_BYTES);
        smem_set = 1;
    }

    dim3 blk(256);
    dim3 g256(256 / BN, (NROWS + BM - 1) / BM);   // (2, 416)
    dim3 g384(NFUSE / BN, (NROWS + BM - 1) / BM); // (3, 416)

    concat_wb<<<(CC * NFUSE + 255) / 256, 256>>>(W_off, W_attn, b_off, b_attn,
                                                 p_Wf, p_bf);
    gemm_tf32_bias<<<g256, blk, SMEM_BYTES>>>(input_flatten, Wv, bv, p_value,
                                              NROWS, 256);
    gemm_tf32_bias<<<g384, blk, SMEM_BYTES>>>(query, p_Wf, p_bf, p_oa,
                                              NROWS, NFUSE);
    msda_sample<<<NROWS, 256>>>(refpts);
    gemm_tf32_bias<<<g256, blk, SMEM_BYTES>>>(p_ms, Wo, bo, out, NROWS, 256);
}

// round 9
// speedup vs baseline: 1.1815x; 1.1815x over previous
#include <cuda_runtime.h>
#include <cuda_fp16.h>
#include <math.h>
#include <stdint.h>

// ---------------- problem constants (static in reference) ----------------
#define NB 4
#define LQ 13294
#define LEN_IN 13294
#define CC 256
#define NROWS (NB * LQ)   // 53176
#define NFUSE 384         // 256 offset logits + 128 attn logits

__device__ __constant__ int c_H[4]     = {100, 50, 25, 13};
__device__ __constant__ int c_W[4]     = {100, 50, 25, 13};
__device__ __constant__ int c_start[4] = {0, 10000, 12500, 13125};

// ---------------- scratch (device globals, no allocation) ----------------
__device__ float g_value[NROWS * CC];     // value projection
__device__ float g_oa[NROWS * NFUSE];     // fused [off(256) | attn(128)] logits
__device__ float g_ms[NROWS * CC];        // sampled output
__device__ float g_Wf[CC * NFUSE];        // concatenated [W_off | W_attn]
__device__ float g_bf[NFUSE];             // concatenated [b_off | b_attn]

// ---------------- prep: concat weights/biases ----------------
__global__ void concat_wb(const float* __restrict__ W_off,
                          const float* __restrict__ W_attn,
                          const float* __restrict__ b_off,
                          const float* __restrict__ b_attn,
                          float* __restrict__ Wf, float* __restrict__ bf)
{
    int i = blockIdx.x * 256 + threadIdx.x;
    if (i < CC * NFUSE) {
        int k = i / NFUSE, c = i % NFUSE;
        Wf[i] = (c < 256) ? W_off[k * 256 + c] : W_attn[k * 128 + (c - 256)];
    }
    if (i < NFUSE) bf[i] = (i < 256) ? b_off[i] : b_attn[i - 256];
}

// ---------------- fp16 tensor-core GEMM (m16n8k16, fp32 accum) ------------
// C(Mrows x Ncols) = A(Mrows x 256) @ B(256 x Ncols) + bias
// block tile 128x128x32, 8 warps (4 in M x 2 in N), warp tile 32x64
#define BM 128
#define BN 128
#define BK 32
#define APSTRIDE 20    // uint32 per A row (16 packed + 4 pad): banks (20r+c)%32 distinct
#define BPSTRIDE 136   // uint32 per B packed-k row (128 + 8 pad): banks 8c+r distinct

// pack two fp32 -> fp16x2 (lo in low half)
__device__ __forceinline__ uint32_t pack_h2(float lo, float hi) {
    uint32_t u;
    asm("cvt.rn.f16x2.f32 %0, %1, %2;" : "=r"(u) : "f"(hi), "f"(lo));
    return u;
}

__device__ __forceinline__ void mma_f16(float* d, const uint32_t* a,
                                        uint32_t b0, uint32_t b1) {
    asm volatile(
        "mma.sync.aligned.m16n8k16.row.col.f32.f16.f16.f32 "
        "{%0,%1,%2,%3},{%4,%5,%6,%7},{%8,%9},{%0,%1,%2,%3};"
        : "+f"(d[0]), "+f"(d[1]), "+f"(d[2]), "+f"(d[3])
        : "r"(a[0]), "r"(a[1]), "r"(a[2]), "r"(a[3]), "r"(b0), "r"(b1));
}

__global__ __launch_bounds__(256, 2) void gemm_f16_bias(
    const float* __restrict__ A, const float* __restrict__ B,
    const float* __restrict__ bias, float* __restrict__ Cmat,
    int Mrows, int Ncols)
{
    __shared__ uint32_t As[BM][APSTRIDE];      // packed k-pairs, [m][k/2]
    __shared__ uint32_t Bs[BK / 2][BPSTRIDE];  // packed k-pairs, [k/2][n]

    const int tid  = threadIdx.x;
    const int lane = tid & 31;
    const int wid  = tid >> 5;
    const int wm   = (wid & 3) * 32;
    const int wn   = (wid >> 2) * 64;
    const int row0 = blockIdx.y * BM;
    const int col0 = blockIdx.x * BN;

    const int r  = lane >> 2;
    const int c  = lane & 3;

    // A load mapping: idx = tid + 256j (j<4): m = idx>>3, kf = (idx&7)*4
    int a_m[4], a_kf[4];
    bool a_ok[4];
    #pragma unroll
    for (int j = 0; j < 4; j++) {
        int idx = tid + 256 * j;
        a_m[j]  = idx >> 3;
        a_kf[j] = (idx & 7) << 2;
        a_ok[j] = (row0 + a_m[j]) < Mrows;
    }
    // B load mapping: idx = tid + 256j (j<2): k2 = idx>>5 (row-pair), nseg = (idx&31)*4
    int b_k2[2], b_ns[2];
    #pragma unroll
    for (int j = 0; j < 2; j++) {
        int idx = tid + 256 * j;
        b_k2[j] = idx >> 5;
        b_ns[j] = (idx & 31) << 2;
    }

    float acc[2][8][4];
    #pragma unroll
    for (int mt = 0; mt < 2; mt++)
        #pragma unroll
        for (int nt = 0; nt < 8; nt++)
            #pragma unroll
            for (int i = 0; i < 4; i++) acc[mt][nt][i] = 0.f;

    float4 ra[4], rb0[2], rb1[2];

    // prologue: load k-tile 0
    #pragma unroll
    for (int j = 0; j < 4; j++)
        ra[j] = a_ok[j] ? *reinterpret_cast<const float4*>(
                    A + (size_t)(row0 + a_m[j]) * CC + a_kf[j])
                        : make_float4(0.f, 0.f, 0.f, 0.f);
    #pragma unroll
    for (int j = 0; j < 2; j++) {
        rb0[j] = *reinterpret_cast<const float4*>(
                    B + (size_t)(2 * b_k2[j]) * Ncols + col0 + b_ns[j]);
        rb1[j] = *reinterpret_cast<const float4*>(
                    B + (size_t)(2 * b_k2[j] + 1) * Ncols + col0 + b_ns[j]);
    }

    #pragma unroll
    for (int kt = 0; kt < CC / BK; kt++) {
        // commit current regs -> smem (fp16 pack)
        #pragma unroll
        for (int j = 0; j < 4; j++) {
            uint2 u;
            u.x = pack_h2(ra[j].x, ra[j].y);
            u.y = pack_h2(ra[j].z, ra[j].w);
            *reinterpret_cast<uint2*>(&As[a_m[j]][a_kf[j] >> 1]) = u;
        }
        #pragma unroll
        for (int j = 0; j < 2; j++) {
            uint4 v;
            v.x = pack_h2(rb0[j].x, rb1[j].x);
            v.y = pack_h2(rb0[j].y, rb1[j].y);
            v.z = pack_h2(rb0[j].z, rb1[j].z);
            v.w = pack_h2(rb0[j].w, rb1[j].w);
            *reinterpret_cast<uint4*>(&Bs[b_k2[j]][b_ns[j]]) = v;
        }
        __syncthreads();

        // prefetch next k-tile into registers (overlaps MMA below)
        if (kt < CC / BK - 1) {
            const int k0 = (kt + 1) * BK;
            #pragma unroll
            for (int j = 0; j < 4; j++)
                ra[j] = a_ok[j] ? *reinterpret_cast<const float4*>(
                            A + (size_t)(row0 + a_m[j]) * CC + k0 + a_kf[j])
                                : make_float4(0.f, 0.f, 0.f, 0.f);
            #pragma unroll
            for (int j = 0; j < 2; j++) {
                rb0[j] = *reinterpret_cast<const float4*>(
                            B + (size_t)(k0 + 2 * b_k2[j]) * Ncols + col0 + b_ns[j]);
                rb1[j] = *reinterpret_cast<const float4*>(
                            B + (size_t)(k0 + 2 * b_k2[j] + 1) * Ncols + col0 + b_ns[j]);
            }
        }

        // 2 k16 slices per tile
        #pragma unroll
        for (int ks = 0; ks < 2; ks++) {
            const int kk = ks * 8;     // packed uint32 offset
            uint32_t afr[2][4];
            #pragma unroll
            for (int mt = 0; mt < 2; mt++) {
                int mbase = wm + mt * 16 + r;
                afr[mt][0] = As[mbase][kk + c];
                afr[mt][1] = As[mbase + 8][kk + c];
                afr[mt][2] = As[mbase][kk + c + 4];
                afr[mt][3] = As[mbase + 8][kk + c + 4];
            }
            #pragma unroll
            for (int nt = 0; nt < 8; nt++) {
                int nbase = wn + nt * 8 + r;
                uint32_t b0 = Bs[kk + c][nbase];
                uint32_t b1 = Bs[kk + c + 4][nbase];
                mma_f16(acc[0][nt], afr[0], b0, b1);
                mma_f16(acc[1][nt], afr[1], b0, b1);
            }
        }
        __syncthreads();
    }

    const int c2 = c * 2;
    #pragma unroll
    for (int mt = 0; mt < 2; mt++) {
        int row = row0 + wm + mt * 16 + r;
        #pragma unroll
        for (int nt = 0; nt < 8; nt++) {
            int col = col0 + wn + nt * 8 + c2;
            float b0 = __ldg(bias + col);
            float b1 = __ldg(bias + col + 1);
            if (row < Mrows) {
                float2 v = make_float2(acc[mt][nt][0] + b0, acc[mt][nt][1] + b1);
                *reinterpret_cast<float2*>(Cmat + (size_t)row * Ncols + col) = v;
            }
            if (row + 8 < Mrows) {
                float2 v = make_float2(acc[mt][nt][2] + b0, acc[mt][nt][3] + b1);
                *reinterpret_cast<float2*>(Cmat + (size_t)(row + 8) * Ncols + col) = v;
            }
        }
    }
}

// ---------------- sampling: one warp per (n, q, m) ----------------
__global__ __launch_bounds__(256) void msda_sample(const float* __restrict__ refpts)
{
    __shared__ float2 s_aw[8][64];      // per warp: 64 (weight, f4-offset) pairs

    const int nq = blockIdx.x;           // n*LQ + q
    const int m = threadIdx.x >> 5;      // head
    const int lane = threadIdx.x & 31;
    const int n = nq / LQ;

    {
        const int p = lane & 15;
        const int l = p >> 2;
        const int half = lane >> 4;      // dy

        float logit = g_oa[(size_t)nq * NFUSE + 256 + m * 16 + p];
        float mx = logit;
        #pragma unroll
        for (int o = 8; o >= 1; o >>= 1)
            mx = fmaxf(mx, __shfl_xor_sync(0xffffffffu, mx, o, 16));
        float e = __expf(logit - mx);
        float s = e;
        #pragma unroll
        for (int o = 8; o >= 1; o >>= 1)
            s += __shfl_xor_sync(0xffffffffu, s, o, 16);
        float prob = e / s;

        float2 offv = *reinterpret_cast<const float2*>(
            g_oa + (size_t)nq * NFUSE + m * 32 + 2 * p);
        float2 refv = *reinterpret_cast<const float2*>(
            refpts + (size_t)nq * 8 + 2 * l);

        const int Wi = c_W[l], Hi = c_H[l];
        const float Wf = (float)Wi, Hf = (float)Hi;

        float x = fmaf(refv.x, Wf, offv.x) - 0.5f;
        float y = fmaf(refv.y, Hf, offv.y) - 0.5f;
        float x0f = floorf(x), y0f = floorf(y);
        float wx = x - x0f, wy = y - y0f;
        int x0 = (int)x0f, y0 = (int)y0f;
        int x1 = x0 + 1;
        int yi = y0 + half;

        float vx0 = (x0 >= 0 && x0 < Wi) ? 1.f : 0.f;
        float vx1 = (x1 >= 0 && x1 < Wi) ? 1.f : 0.f;
        float vy  = (yi >= 0 && yi < Hi) ? 1.f : 0.f;
        float wyv = half ? wy : (1.f - wy);

        int cx0 = min(max(x0, 0), Wi - 1);
        int cx1 = min(max(x1, 0), Wi - 1);
        int cyi = min(max(yi, 0), Hi - 1);

        int rbase = (c_start[l] + cyi * Wi) * 64;   // float4 units
        int o0 = rbase + cx0 * 64;
        int o1 = rbase + cx1 * 64;

        float pv = prob * wyv * vy;
        float w0 = (1.f - wx) * pv * vx0;
        float w1 = wx * pv * vx1;

        float4 st = make_float4(w0, __int_as_float(o0),
                                w1, __int_as_float(o1));
        *reinterpret_cast<float4*>(&s_aw[m][p * 4 + half * 2]) = st;
    }
    __syncwarp();

    const int g  = lane >> 3;
    const int lg = lane & 7;
    const float4* vbase = reinterpret_cast<const float4*>(
        g_value + (size_t)n * LEN_IN * CC + m * 32) + lg;

    float4 acc = make_float4(0.f, 0.f, 0.f, 0.f);
    #pragma unroll
    for (int i = 0; i < 16; i++) {
        float2 e = s_aw[m][i * 4 + g];
        float4 v = __ldg(vbase + __float_as_int(e.y));
        acc.x = fmaf(v.x, e.x, acc.x);
        acc.y = fmaf(v.y, e.x, acc.y);
        acc.z = fmaf(v.z, e.x, acc.z);
        acc.w = fmaf(v.w, e.x, acc.w);
    }

    #pragma unroll
    for (int o = 8; o <= 16; o <<= 1) {
        acc.x += __shfl_xor_sync(0xffffffffu, acc.x, o);
        acc.y += __shfl_xor_sync(0xffffffffu, acc.y, o);
        acc.z += __shfl_xor_sync(0xffffffffu, acc.z, o);
        acc.w += __shfl_xor_sync(0xffffffffu, acc.w, o);
    }

    if (lane < 8) {
        *reinterpret_cast<float4*>(
            g_ms + (size_t)nq * 256 + m * 32 + lg * 4) = acc;
    }
}

// ---------------- launch ----------------
extern "C" void kernel_launch(void* const* d_in, const int* in_sizes, int n_in,
                              void* d_out, int out_size)
{
    const float* query         = (const float*)d_in[0];
    const float* refpts        = (const float*)d_in[1];
    const float* input_flatten = (const float*)d_in[2];
    const float* Wv     = (const float*)d_in[5];
    const float* bv     = (const float*)d_in[6];
    const float* W_off  = (const float*)d_in[7];
    const float* b_off  = (const float*)d_in[8];
    const float* W_attn = (const float*)d_in[9];
    const float* b_attn = (const float*)d_in[10];
    const float* Wo     = (const float*)d_in[11];
    const float* bo     = (const float*)d_in[12];
    float* out = (float*)d_out;

    float *p_value, *p_oa, *p_ms, *p_Wf, *p_bf;
    cudaGetSymbolAddress((void**)&p_value, g_value);
    cudaGetSymbolAddress((void**)&p_oa,    g_oa);
    cudaGetSymbolAddress((void**)&p_ms,    g_ms);
    cudaGetSymbolAddress((void**)&p_Wf,    g_Wf);
    cudaGetSymbolAddress((void**)&p_bf,    g_bf);

    dim3 blk(256);
    dim3 g256(256 / BN, (NROWS + BM - 1) / BM);   // (2, 416)
    dim3 g384(NFUSE / BN, (NROWS + BM - 1) / BM); // (3, 416)

    concat_wb<<<(CC * NFUSE + 255) / 256, 256>>>(W_off, W_attn, b_off, b_attn,
                                                 p_Wf, p_bf);
    gemm_f16_bias<<<g256, blk>>>(input_flatten, Wv, bv, p_value, NROWS, 256);
    gemm_f16_bias<<<g384, blk>>>(query, p_Wf, p_bf, p_oa, NROWS, NFUSE);
    msda_sample<<<NROWS, 256>>>(refpts);
    gemm_f16_bias<<<g256, blk>>>(p_ms, Wo, bo, out, NROWS, 256);
}

// round 10
// speedup vs baseline: 1.3555x; 1.1472x over previous
#include <cuda_runtime.h>
#include <cuda_fp16.h>
#include <math.h>
#include <stdint.h>

// ---------------- problem constants (static in reference) ----------------
#define NB 4
#define LQ 13294
#define LEN_IN 13294
#define CC 256
#define NROWS (NB * LQ)   // 53176
#define NFUSE 384

__device__ __constant__ int c_H[4]     = {100, 50, 25, 13};
__device__ __constant__ int c_W[4]     = {100, 50, 25, 13};
__device__ __constant__ int c_start[4] = {0, 10000, 12500, 13125};

// ---------------- scratch (device globals, no allocation) ----------------
// value, head-major fp16: [(n*8+head)][spatial][16 x half2]
__device__ uint32_t g_valueh[NROWS * 128];
__device__ float    g_oa[NROWS * NFUSE];   // fused [off(256)|attn(128)] logits, fp32
__device__ uint32_t g_msh[NROWS * 128];    // sampled output, row-major fp16 k-pairs
__device__ uint32_t g_Wvh[128 * CC];       // Wv  fp16 k-pair packed [k2][n]
__device__ uint32_t g_Wfh[128 * NFUSE];    // [W_off|W_attn] packed
__device__ uint32_t g_Woh[128 * CC];       // Wo packed
__device__ float    g_bf[NFUSE];

// pack two fp32 -> fp16x2 (lo in low half)
__device__ __forceinline__ uint32_t pack_h2(float lo, float hi) {
    uint32_t u;
    asm("cvt.rn.f16x2.f32 %0, %1, %2;" : "=r"(u) : "f"(hi), "f"(lo));
    return u;
}

// ---------------- prep: pack weights to fp16 k-pair layout ----------------
__global__ void prep(const float* __restrict__ Wv,
                     const float* __restrict__ W_off,
                     const float* __restrict__ W_attn,
                     const float* __restrict__ Wo,
                     const float* __restrict__ b_off,
                     const float* __restrict__ b_attn)
{
    int i = blockIdx.x * 256 + threadIdx.x;
    if (i < 128 * CC) {
        int k2 = i / CC, n = i % CC;
        g_Wvh[i] = pack_h2(Wv[(2 * k2) * CC + n], Wv[(2 * k2 + 1) * CC + n]);
        g_Woh[i] = pack_h2(Wo[(2 * k2) * CC + n], Wo[(2 * k2 + 1) * CC + n]);
    }
    if (i < 128 * NFUSE) {
        int k2 = i / NFUSE, n = i % NFUSE;
        float lo = (n < 256) ? W_off[(2 * k2) * 256 + n]
                             : W_attn[(2 * k2) * 128 + (n - 256)];
        float hi = (n < 256) ? W_off[(2 * k2 + 1) * 256 + n]
                             : W_attn[(2 * k2 + 1) * 128 + (n - 256)];
        g_Wfh[i] = pack_h2(lo, hi);
    }
    if (i < NFUSE) g_bf[i] = (i < 256) ? b_off[i] : b_attn[i - 256];
}

// ---------------- fp16 tensor-core GEMM (m16n8k16, fp32 accum) ------------
#define BM 128
#define BN 128
#define BK 32
#define APSTRIDE 20
#define BPSTRIDE 136

__device__ __forceinline__ void mma_f16(float* d, const uint32_t* a,
                                        uint32_t b0, uint32_t b1) {
    asm volatile(
        "mma.sync.aligned.m16n8k16.row.col.f32.f16.f16.f32 "
        "{%0,%1,%2,%3},{%4,%5,%6,%7},{%8,%9},{%0,%1,%2,%3};"
        : "+f"(d[0]), "+f"(d[1]), "+f"(d[2]), "+f"(d[3])
        : "r"(a[0]), "r"(a[1]), "r"(a[2]), "r"(a[3]), "r"(b0), "r"(b1));
}

// AMODE: 0 = A fp32 row-major [Mrows][256]; 1 = A fp16 k-pair packed [Mrows][128]u32
// CMODE: 0 = C fp32 row-major; 1 = C fp16 head-major value layout
template <int AMODE, int CMODE>
__global__ __launch_bounds__(256, 2) void gemm_f16(
    const void* __restrict__ Ap, const uint32_t* __restrict__ Bh,
    const float* __restrict__ bias, void* __restrict__ Cp,
    int Mrows, int Ncols)
{
    __shared__ uint32_t As[BM][APSTRIDE];      // packed k-pairs [m][k2]
    __shared__ uint32_t Bs[BK / 2][BPSTRIDE];  // packed k-pairs [k2][n]

    const float*    A32 = (const float*)Ap;
    const uint32_t* A16 = (const uint32_t*)Ap;

    const int tid  = threadIdx.x;
    const int lane = tid & 31;
    const int wid  = tid >> 5;
    const int wm   = (wid & 3) * 32;
    const int wn   = (wid >> 2) * 64;
    const int row0 = blockIdx.y * BM;
    const int col0 = blockIdx.x * BN;
    const int r = lane >> 2;
    const int c = lane & 3;

    // B mapping: 2 chunks/thread
    int b_k2[2], b_ns[2];
    #pragma unroll
    for (int j = 0; j < 2; j++) {
        int idx = tid + 256 * j;
        b_k2[j] = idx >> 5;
        b_ns[j] = (idx & 31) << 2;
    }

    // A mappings
    int a_m4[4], a_kf[4];  bool a_ok4[4];   // AMODE 0
    int a_m2[2], a_kp[2];  bool a_ok2[2];   // AMODE 1
    if (AMODE == 0) {
        #pragma unroll
        for (int j = 0; j < 4; j++) {
            int idx = tid + 256 * j;
            a_m4[j]  = idx >> 3;
            a_kf[j]  = (idx & 7) << 2;
            a_ok4[j] = (row0 + a_m4[j]) < Mrows;
        }
    } else {
        #pragma unroll
        for (int j = 0; j < 2; j++) {
            int idx = tid + 256 * j;          // 0..511
            a_m2[j]  = idx >> 2;              // 0..127
            a_kp[j]  = (idx & 3) << 2;        // 0,4,8,12
            a_ok2[j] = (row0 + a_m2[j]) < Mrows;
        }
    }

    float acc[2][8][4];
    #pragma unroll
    for (int mt = 0; mt < 2; mt++)
        #pragma unroll
        for (int nt = 0; nt < 8; nt++)
            #pragma unroll
            for (int i = 0; i < 4; i++) acc[mt][nt][i] = 0.f;

    float4 ra[4];
    uint4  rah[2], rbh[2];

    // prologue: k-tile 0
    if (AMODE == 0) {
        #pragma unroll
        for (int j = 0; j < 4; j++)
            ra[j] = a_ok4[j] ? *reinterpret_cast<const float4*>(
                        A32 + (size_t)(row0 + a_m4[j]) * CC + a_kf[j])
                             : make_float4(0.f, 0.f, 0.f, 0.f);
    } else {
        #pragma unroll
        for (int j = 0; j < 2; j++)
            rah[j] = a_ok2[j] ? *reinterpret_cast<const uint4*>(
                        A16 + (size_t)(row0 + a_m2[j]) * 128 + a_kp[j])
                              : make_uint4(0, 0, 0, 0);
    }
    #pragma unroll
    for (int j = 0; j < 2; j++)
        rbh[j] = *reinterpret_cast<const uint4*>(
                    Bh + (size_t)b_k2[j] * Ncols + col0 + b_ns[j]);

    #pragma unroll
    for (int kt = 0; kt < CC / BK; kt++) {
        // commit regs -> smem
        if (AMODE == 0) {
            #pragma unroll
            for (int j = 0; j < 4; j++) {
                uint2 u;
                u.x = pack_h2(ra[j].x, ra[j].y);
                u.y = pack_h2(ra[j].z, ra[j].w);
                *reinterpret_cast<uint2*>(&As[a_m4[j]][a_kf[j] >> 1]) = u;
            }
        } else {
            #pragma unroll
            for (int j = 0; j < 2; j++)
                *reinterpret_cast<uint4*>(&As[a_m2[j]][a_kp[j]]) = rah[j];
        }
        #pragma unroll
        for (int j = 0; j < 2; j++)
            *reinterpret_cast<uint4*>(&Bs[b_k2[j]][b_ns[j]]) = rbh[j];
        __syncthreads();

        // prefetch next tile
        if (kt < CC / BK - 1) {
            const int k0 = (kt + 1) * BK;
            if (AMODE == 0) {
                #pragma unroll
                for (int j = 0; j < 4; j++)
                    ra[j] = a_ok4[j] ? *reinterpret_cast<const float4*>(
                                A32 + (size_t)(row0 + a_m4[j]) * CC + k0 + a_kf[j])
                                     : make_float4(0.f, 0.f, 0.f, 0.f);
            } else {
                #pragma unroll
                for (int j = 0; j < 2; j++)
                    rah[j] = a_ok2[j] ? *reinterpret_cast<const uint4*>(
                                A16 + (size_t)(row0 + a_m2[j]) * 128 +
                                (k0 >> 1) + a_kp[j])
                                      : make_uint4(0, 0, 0, 0);
            }
            #pragma unroll
            for (int j = 0; j < 2; j++)
                rbh[j] = *reinterpret_cast<const uint4*>(
                            Bh + (size_t)((k0 >> 1) + b_k2[j]) * Ncols +
                            col0 + b_ns[j]);
        }

        // 2 k16 slices
        #pragma unroll
        for (int ks = 0; ks < 2; ks++) {
            const int kk = ks * 8;
            uint32_t afr[2][4];
            #pragma unroll
            for (int mt = 0; mt < 2; mt++) {
                int mbase = wm + mt * 16 + r;
                afr[mt][0] = As[mbase][kk + c];
                afr[mt][1] = As[mbase + 8][kk + c];
                afr[mt][2] = As[mbase][kk + c + 4];
                afr[mt][3] = As[mbase + 8][kk + c + 4];
            }
            #pragma unroll
            for (int nt = 0; nt < 8; nt++) {
                int nbase = wn + nt * 8 + r;
                uint32_t b0 = Bs[kk + c][nbase];
                uint32_t b1 = Bs[kk + c + 4][nbase];
                mma_f16(acc[0][nt], afr[0], b0, b1);
                mma_f16(acc[1][nt], afr[1], b0, b1);
            }
        }
        __syncthreads();
    }

    // ---- epilogue ----
    const int c2 = c * 2;
    if (CMODE == 0) {
        float* C32 = (float*)Cp;
        #pragma unroll
        for (int mt = 0; mt < 2; mt++) {
            int row = row0 + wm + mt * 16 + r;
            #pragma unroll
            for (int nt = 0; nt < 8; nt++) {
                int col = col0 + wn + nt * 8 + c2;
                float b0 = __ldg(bias + col);
                float b1 = __ldg(bias + col + 1);
                if (row < Mrows) {
                    float2 v = make_float2(acc[mt][nt][0] + b0, acc[mt][nt][1] + b1);
                    *reinterpret_cast<float2*>(C32 + (size_t)row * Ncols + col) = v;
                }
                if (row + 8 < Mrows) {
                    float2 v = make_float2(acc[mt][nt][2] + b0, acc[mt][nt][3] + b1);
                    *reinterpret_cast<float2*>(C32 + (size_t)(row + 8) * Ncols + col) = v;
                }
            }
        }
    } else {
        // head-major fp16 value layout: [(nb*8+head)*LEN + sp][16 half2]
        uint32_t* C16 = (uint32_t*)Cp;
        #pragma unroll
        for (int mt = 0; mt < 2; mt++) {
            #pragma unroll
            for (int half = 0; half < 2; half++) {
                int row = row0 + wm + mt * 16 + r + half * 8;
                if (row >= Mrows) continue;
                int nb = row / LQ;
                int sp = row - nb * LQ;
                size_t base = ((size_t)(nb * 8) * LEN_IN + sp) * 16;
                #pragma unroll
                for (int nt = 0; nt < 8; nt++) {
                    int col = col0 + wn + nt * 8 + c2;
                    int head = col >> 5, ch = col & 31;
                    float v0 = acc[mt][nt][half * 2 + 0] + __ldg(bias + col);
                    float v1 = acc[mt][nt][half * 2 + 1] + __ldg(bias + col + 1);
                    C16[base + (size_t)head * (LEN_IN * 16) + (ch >> 1)] =
                        pack_h2(v0, v1);
                }
            }
        }
    }
}

// ---------------- sampling: one warp per (n, q, m) ----------------
// value is head-major fp16: per (n,head) plane of LEN_IN rows x 64B.
// Phase 2 gathers uint2 (4 halves) per lane; x-adjacent corners often share
// a 128B line, cutting L1 wavefronts.
__global__ __launch_bounds__(256) void msda_sample(const float* __restrict__ refpts)
{
    __shared__ float2 s_aw[8][64];

    const int nq = blockIdx.x;
    const int m = threadIdx.x >> 5;
    const int lane = threadIdx.x & 31;
    const int n = nq / LQ;

    {
        const int p = lane & 15;
        const int l = p >> 2;
        const int half = lane >> 4;

        float logit = g_oa[(size_t)nq * NFUSE + 256 + m * 16 + p];
        float mx = logit;
        #pragma unroll
        for (int o = 8; o >= 1; o >>= 1)
            mx = fmaxf(mx, __shfl_xor_sync(0xffffffffu, mx, o, 16));
        float e = __expf(logit - mx);
        float s = e;
        #pragma unroll
        for (int o = 8; o >= 1; o >>= 1)
            s += __shfl_xor_sync(0xffffffffu, s, o, 16);
        float prob = e / s;

        float2 offv = *reinterpret_cast<const float2*>(
            g_oa + (size_t)nq * NFUSE + m * 32 + 2 * p);
        float2 refv = *reinterpret_cast<const float2*>(
            refpts + (size_t)nq * 8 + 2 * l);

        const int Wi = c_W[l], Hi = c_H[l];
        const float Wf = (float)Wi, Hf = (float)Hi;

        float x = fmaf(refv.x, Wf, offv.x) - 0.5f;
        float y = fmaf(refv.y, Hf, offv.y) - 0.5f;
        float x0f = floorf(x), y0f = floorf(y);
        float wx = x - x0f, wy = y - y0f;
        int x0 = (int)x0f, y0 = (int)y0f;
        int x1 = x0 + 1;
        int yi = y0 + half;

        float vx0 = (x0 >= 0 && x0 < Wi) ? 1.f : 0.f;
        float vx1 = (x1 >= 0 && x1 < Wi) ? 1.f : 0.f;
        float vy  = (yi >= 0 && yi < Hi) ? 1.f : 0.f;
        float wyv = half ? wy : (1.f - wy);

        int cx0 = min(max(x0, 0), Wi - 1);
        int cx1 = min(max(x1, 0), Wi - 1);
        int cyi = min(max(yi, 0), Hi - 1);

        // offsets in uint2 units: 8 per spatial position
        int rbase = (c_start[l] + cyi * Wi) * 8;
        int o0 = rbase + cx0 * 8;
        int o1 = rbase + cx1 * 8;

        float pv = prob * wyv * vy;
        float w0 = (1.f - wx) * pv * vx0;
        float w1 = wx * pv * vx1;

        float4 st = make_float4(w0, __int_as_float(o0),
                                w1, __int_as_float(o1));
        *reinterpret_cast<float4*>(&s_aw[m][p * 4 + half * 2]) = st;
    }
    __syncwarp();

    const int g  = lane >> 3;
    const int lg = lane & 7;
    const uint2* vbase = reinterpret_cast<const uint2*>(g_valueh) +
                         ((size_t)(n * 8 + m) * LEN_IN) * 8 + lg;

    float4 acc = make_float4(0.f, 0.f, 0.f, 0.f);
    #pragma unroll
    for (int i = 0; i < 16; i++) {
        float2 e = s_aw[m][i * 4 + g];
        uint2 u = __ldg(vbase + __float_as_int(e.y));
        float2 f0 = __half22float2(*reinterpret_cast<const __half2*>(&u.x));
        float2 f1 = __half22float2(*reinterpret_cast<const __half2*>(&u.y));
        acc.x = fmaf(f0.x, e.x, acc.x);
        acc.y = fmaf(f0.y, e.x, acc.y);
        acc.z = fmaf(f1.x, e.x, acc.z);
        acc.w = fmaf(f1.y, e.x, acc.w);
    }

    #pragma unroll
    for (int o = 8; o <= 16; o <<= 1) {
        acc.x += __shfl_xor_sync(0xffffffffu, acc.x, o);
        acc.y += __shfl_xor_sync(0xffffffffu, acc.y, o);
        acc.z += __shfl_xor_sync(0xffffffffu, acc.z, o);
        acc.w += __shfl_xor_sync(0xffffffffu, acc.w, o);
    }

    if (lane < 8) {
        uint2 o;
        o.x = pack_h2(acc.x, acc.y);
        o.y = pack_h2(acc.z, acc.w);
        reinterpret_cast<uint2*>(g_msh)[(size_t)nq * 64 + m * 8 + lg] = o;
    }
}

// ---------------- launch ----------------
extern "C" void kernel_launch(void* const* d_in, const int* in_sizes, int n_in,
                              void* d_out, int out_size)
{
    const float* query         = (const float*)d_in[0];
    const float* refpts        = (const float*)d_in[1];
    const float* input_flatten = (const float*)d_in[2];
    const float* Wv     = (const float*)d_in[5];
    const float* bv     = (const float*)d_in[6];
    const float* W_off  = (const float*)d_in[7];
    const float* b_off  = (const float*)d_in[8];
    const float* W_attn = (const float*)d_in[9];
    const float* b_attn = (const float*)d_in[10];
    const float* Wo     = (const float*)d_in[11];
    const float* bo     = (const float*)d_in[12];
    float* out = (float*)d_out;

    void *p_valueh, *p_oa, *p_msh, *p_Wvh, *p_Wfh, *p_Woh, *p_bf;
    cudaGetSymbolAddress(&p_valueh, g_valueh);
    cudaGetSymbolAddress(&p_oa,     g_oa);
    cudaGetSymbolAddress(&p_msh,    g_msh);
    cudaGetSymbolAddress(&p_Wvh,    g_Wvh);
    cudaGetSymbolAddress(&p_Wfh,    g_Wfh);
    cudaGetSymbolAddress(&p_Woh,    g_Woh);
    cudaGetSymbolAddress(&p_bf,     g_bf);

    dim3 blk(256);
    dim3 g256(256 / BN, (NROWS + BM - 1) / BM);   // (2, 416)
    dim3 g384(NFUSE / BN, (NROWS + BM - 1) / BM); // (3, 416)

    prep<<<(128 * NFUSE + 255) / 256, 256>>>(Wv, W_off, W_attn, Wo,
                                             b_off, b_attn);
    // value projection -> head-major fp16
    gemm_f16<0, 1><<<g256, blk>>>(input_flatten, (const uint32_t*)p_Wvh,
                                  bv, p_valueh, NROWS, 256);
    // fused offsets + attn logits -> fp32
    gemm_f16<0, 0><<<g384, blk>>>(query, (const uint32_t*)p_Wfh,
                                  (const float*)p_bf, p_oa, NROWS, NFUSE);
    // deformable sampling -> fp16 packed ms
    msda_sample<<<NROWS, 256>>>(refpts);
    // output projection (A = fp16 packed ms) -> fp32 out
    gemm_f16<1, 0><<<g256, blk>>>(p_msh, (const uint32_t*)p_Woh,
                                  bo, out, NROWS, 256);
}

// round 11
// speedup vs baseline: 1.3713x; 1.0116x over previous
#include <cuda_runtime.h>
#include <cuda_fp16.h>
#include <math.h>
#include <stdint.h>

// ---------------- problem constants (static in reference) ----------------
#define NB 4
#define LQ 13294
#define LEN_IN 13294
#define CC 256
#define NROWS (NB * LQ)   // 53176
#define NFUSE 384

__device__ __constant__ int c_H[4]     = {100, 50, 25, 13};
__device__ __constant__ int c_W[4]     = {100, 50, 25, 13};
__device__ __constant__ int c_start[4] = {0, 10000, 12500, 13125};

// ---------------- scratch (device globals, no allocation) ----------------
// value, head-major fp16: [(n*8+head)][spatial][16 x half2]
__device__ uint32_t g_valueh[NROWS * 128];
__device__ float    g_oa[NROWS * NFUSE];   // fused [off|attn] logits, fp32
__device__ uint32_t g_msh[NROWS * 128];    // sampled output, fp16 k-pairs
// weights, n-major fp16 k-pair packed: row n holds k2 = 0..127
__device__ uint32_t g_Wvh[CC * 128];
__device__ uint32_t g_Wfh[NFUSE * 128];
__device__ uint32_t g_Woh[CC * 128];
__device__ float    g_bf[NFUSE];

// pack two fp32 -> fp16x2 (lo in low half)
__device__ __forceinline__ uint32_t pack_h2(float lo, float hi) {
    uint32_t u;
    asm("cvt.rn.f16x2.f32 %0, %1, %2;" : "=r"(u) : "f"(hi), "f"(lo));
    return u;
}

// ---------------- prep: pack weights to fp16, n-major ----------------
__global__ void prep(const float* __restrict__ Wv,
                     const float* __restrict__ W_off,
                     const float* __restrict__ W_attn,
                     const float* __restrict__ Wo,
                     const float* __restrict__ b_off,
                     const float* __restrict__ b_attn)
{
    int i = blockIdx.x * 256 + threadIdx.x;
    if (i < CC * 128) {
        int n = i >> 7, k2 = i & 127;
        g_Wvh[i] = pack_h2(Wv[(2 * k2) * CC + n], Wv[(2 * k2 + 1) * CC + n]);
        g_Woh[i] = pack_h2(Wo[(2 * k2) * CC + n], Wo[(2 * k2 + 1) * CC + n]);
    }
    if (i < NFUSE * 128) {
        int n = i >> 7, k2 = i & 127;
        float lo = (n < 256) ? W_off[(2 * k2) * 256 + n]
                             : W_attn[(2 * k2) * 128 + (n - 256)];
        float hi = (n < 256) ? W_off[(2 * k2 + 1) * 256 + n]
                             : W_attn[(2 * k2 + 1) * 128 + (n - 256)];
        g_Wfh[i] = pack_h2(lo, hi);
    }
    if (i < NFUSE) g_bf[i] = (i < 256) ? b_off[i] : b_attn[i - 256];
}

// ---------------- fp16 tensor-core GEMM with ldmatrix ----------------
#define BM 128
#define BN 128
#define BK 32
#define PSTR 20   // u32 row stride (16 payload + 4 pad) -> ldmatrix conflict-free

__device__ __forceinline__ void mma_f16(float* d, const uint32_t* a,
                                        uint32_t b0, uint32_t b1) {
    asm volatile(
        "mma.sync.aligned.m16n8k16.row.col.f32.f16.f16.f32 "
        "{%0,%1,%2,%3},{%4,%5,%6,%7},{%8,%9},{%0,%1,%2,%3};"
        : "+f"(d[0]), "+f"(d[1]), "+f"(d[2]), "+f"(d[3])
        : "r"(a[0]), "r"(a[1]), "r"(a[2]), "r"(a[3]), "r"(b0), "r"(b1));
}

__device__ __forceinline__ void ldsm_x4(uint32_t* r, uint32_t addr) {
    asm volatile("ldmatrix.sync.aligned.m8n8.x4.shared.b16 {%0,%1,%2,%3}, [%4];"
        : "=r"(r[0]), "=r"(r[1]), "=r"(r[2]), "=r"(r[3]) : "r"(addr));
}

// AMODE: 0 = A fp32 row-major [Mrows][256]; 1 = A fp16 k-pair packed [Mrows][128]u32
// CMODE: 0 = C fp32 row-major; 1 = C fp16 head-major value layout
template <int AMODE, int CMODE>
__global__ __launch_bounds__(256, 2) void gemm_f16(
    const void* __restrict__ Ap, const uint32_t* __restrict__ Bh,
    const float* __restrict__ bias, void* __restrict__ Cp,
    int Mrows, int Ncols)
{
    __shared__ uint32_t As[BM][PSTR];   // row m: 32 k-halves (16 u32) + pad
    __shared__ uint32_t Bs[BN][PSTR];   // row n: 32 k-halves (16 u32) + pad

    const float*    A32 = (const float*)Ap;
    const uint32_t* A16 = (const uint32_t*)Ap;

    const int tid  = threadIdx.x;
    const int lane = tid & 31;
    const int wid  = tid >> 5;
    const int wm   = (wid & 3) * 32;
    const int wn   = (wid >> 2) * 64;
    const int row0 = blockIdx.y * BM;
    const int col0 = blockIdx.x * BN;
    const int r = lane >> 2;
    const int c = lane & 3;

    const uint32_t as_base = (uint32_t)__cvta_generic_to_shared(&As[0][0]);
    const uint32_t bs_base = (uint32_t)__cvta_generic_to_shared(&Bs[0][0]);

    // ldmatrix per-lane base addresses (bytes), + ks*32 at use
    uint32_t a_addr[2], b_addr[4];
    {
        int arow = ((lane >> 3) & 1) * 8 + (lane & 7);
        int achk = (lane >> 4) * 16;
        #pragma unroll
        for (int mt = 0; mt < 2; mt++)
            a_addr[mt] = as_base + (wm + mt * 16 + arow) * (PSTR * 4) + achk;
        int brow = (lane >> 4) * 8 + (lane & 7);
        int bchk = ((lane >> 3) & 1) * 16;
        #pragma unroll
        for (int ntp = 0; ntp < 4; ntp++)
            b_addr[ntp] = bs_base + (wn + ntp * 16 + brow) * (PSTR * 4) + bchk;
    }

    // B fill mapping: 2 uint4/thread, n = idx>>2, jj = idx&3
    int b_n[2], b_jj[2];
    #pragma unroll
    for (int j = 0; j < 2; j++) {
        int idx = tid + 256 * j;
        b_n[j]  = idx >> 2;
        b_jj[j] = idx & 3;
    }

    // A fill mappings
    int a_m4[4], a_kf[4];  bool a_ok4[4];   // AMODE 0
    int a_m2[2], a_kp[2];  bool a_ok2[2];   // AMODE 1
    if (AMODE == 0) {
        #pragma unroll
        for (int j = 0; j < 4; j++) {
            int idx = tid + 256 * j;
            a_m4[j]  = idx >> 3;
            a_kf[j]  = (idx & 7) << 2;
            a_ok4[j] = (row0 + a_m4[j]) < Mrows;
        }
    } else {
        #pragma unroll
        for (int j = 0; j < 2; j++) {
            int idx = tid + 256 * j;
            a_m2[j]  = idx >> 2;
            a_kp[j]  = (idx & 3) << 2;
            a_ok2[j] = (row0 + a_m2[j]) < Mrows;
        }
    }

    float acc[2][8][4];
    #pragma unroll
    for (int mt = 0; mt < 2; mt++)
        #pragma unroll
        for (int nt = 0; nt < 8; nt++)
            #pragma unroll
            for (int i = 0; i < 4; i++) acc[mt][nt][i] = 0.f;

    float4 ra[4];
    uint4  rah[2], rbh[2];

    // prologue: k-tile 0 loads
    if (AMODE == 0) {
        #pragma unroll
        for (int j = 0; j < 4; j++)
            ra[j] = a_ok4[j] ? *reinterpret_cast<const float4*>(
                        A32 + (size_t)(row0 + a_m4[j]) * CC + a_kf[j])
                             : make_float4(0.f, 0.f, 0.f, 0.f);
    } else {
        #pragma unroll
        for (int j = 0; j < 2; j++)
            rah[j] = a_ok2[j] ? *reinterpret_cast<const uint4*>(
                        A16 + (size_t)(row0 + a_m2[j]) * 128 + a_kp[j])
                              : make_uint4(0, 0, 0, 0);
    }
    #pragma unroll
    for (int j = 0; j < 2; j++)
        rbh[j] = *reinterpret_cast<const uint4*>(
                    Bh + (size_t)(col0 + b_n[j]) * 128 + b_jj[j] * 4);

    #pragma unroll
    for (int kt = 0; kt < CC / BK; kt++) {
        // commit regs -> smem
        if (AMODE == 0) {
            #pragma unroll
            for (int j = 0; j < 4; j++) {
                uint2 u;
                u.x = pack_h2(ra[j].x, ra[j].y);
                u.y = pack_h2(ra[j].z, ra[j].w);
                *reinterpret_cast<uint2*>(&As[a_m4[j]][a_kf[j] >> 1]) = u;
            }
        } else {
            #pragma unroll
            for (int j = 0; j < 2; j++)
                *reinterpret_cast<uint4*>(&As[a_m2[j]][a_kp[j]]) = rah[j];
        }
        #pragma unroll
        for (int j = 0; j < 2; j++)
            *reinterpret_cast<uint4*>(&Bs[b_n[j]][b_jj[j] * 4]) = rbh[j];
        __syncthreads();

        // prefetch next tile
        if (kt < CC / BK - 1) {
            const int k0 = (kt + 1) * BK;
            if (AMODE == 0) {
                #pragma unroll
                for (int j = 0; j < 4; j++)
                    ra[j] = a_ok4[j] ? *reinterpret_cast<const float4*>(
                                A32 + (size_t)(row0 + a_m4[j]) * CC + k0 + a_kf[j])
                                     : make_float4(0.f, 0.f, 0.f, 0.f);
            } else {
                #pragma unroll
                for (int j = 0; j < 2; j++)
                    rah[j] = a_ok2[j] ? *reinterpret_cast<const uint4*>(
                                A16 + (size_t)(row0 + a_m2[j]) * 128 +
                                (k0 >> 1) + a_kp[j])
                                      : make_uint4(0, 0, 0, 0);
            }
            #pragma unroll
            for (int j = 0; j < 2; j++)
                rbh[j] = *reinterpret_cast<const uint4*>(
                            Bh + (size_t)(col0 + b_n[j]) * 128 +
                            (k0 >> 1) + b_jj[j] * 4);
        }

        // 2 k16 slices, fragments via ldmatrix
        #pragma unroll
        for (int ks = 0; ks < 2; ks++) {
            const uint32_t koff = ks * 32;
            uint32_t afr[2][4];
            ldsm_x4(afr[0], a_addr[0] + koff);
            ldsm_x4(afr[1], a_addr[1] + koff);
            #pragma unroll
            for (int ntp = 0; ntp < 4; ntp++) {
                uint32_t bfr[4];   // {b0_g0, b1_g0, b0_g1, b1_g1}
                ldsm_x4(bfr, b_addr[ntp] + koff);
                mma_f16(acc[0][2 * ntp + 0], afr[0], bfr[0], bfr[1]);
                mma_f16(acc[1][2 * ntp + 0], afr[1], bfr[0], bfr[1]);
                mma_f16(acc[0][2 * ntp + 1], afr[0], bfr[2], bfr[3]);
                mma_f16(acc[1][2 * ntp + 1], afr[1], bfr[2], bfr[3]);
            }
        }
        __syncthreads();
    }

    // ---- epilogue ----
    const int c2 = c * 2;
    if (CMODE == 0) {
        float* C32 = (float*)Cp;
        #pragma unroll
        for (int mt = 0; mt < 2; mt++) {
            int row = row0 + wm + mt * 16 + r;
            #pragma unroll
            for (int nt = 0; nt < 8; nt++) {
                int col = col0 + wn + nt * 8 + c2;
                float b0 = __ldg(bias + col);
                float b1 = __ldg(bias + col + 1);
                if (row < Mrows) {
                    float2 v = make_float2(acc[mt][nt][0] + b0, acc[mt][nt][1] + b1);
                    *reinterpret_cast<float2*>(C32 + (size_t)row * Ncols + col) = v;
                }
                if (row + 8 < Mrows) {
                    float2 v = make_float2(acc[mt][nt][2] + b0, acc[mt][nt][3] + b1);
                    *reinterpret_cast<float2*>(C32 + (size_t)(row + 8) * Ncols + col) = v;
                }
            }
        }
    } else {
        // head-major fp16 value layout: [(nb*8+head)*LEN + sp][16 half2]
        uint32_t* C16 = (uint32_t*)Cp;
        #pragma unroll
        for (int mt = 0; mt < 2; mt++) {
            #pragma unroll
            for (int half = 0; half < 2; half++) {
                int row = row0 + wm + mt * 16 + r + half * 8;
                if (row >= Mrows) continue;
                int nb = row / LQ;
                int sp = row - nb * LQ;
                size_t base = ((size_t)(nb * 8) * LEN_IN + sp) * 16;
                #pragma unroll
                for (int nt = 0; nt < 8; nt++) {
                    int col = col0 + wn + nt * 8 + c2;
                    int head = col >> 5, ch = col & 31;
                    float v0 = acc[mt][nt][half * 2 + 0] + __ldg(bias + col);
                    float v1 = acc[mt][nt][half * 2 + 1] + __ldg(bias + col + 1);
                    C16[base + (size_t)head * (LEN_IN * 16) + (ch >> 1)] =
                        pack_h2(v0, v1);
                }
            }
        }
    }
}

// ---------------- sampling: one warp per (n, q, m) ----------------
__global__ __launch_bounds__(256) void msda_sample(const float* __restrict__ refpts)
{
    __shared__ float2 s_aw[8][64];

    const int nq = blockIdx.x;
    const int m = threadIdx.x >> 5;
    const int lane = threadIdx.x & 31;
    const int n = nq / LQ;

    {
        const int p = lane & 15;
        const int l = p >> 2;
        const int half = lane >> 4;

        float logit = g_oa[(size_t)nq * NFUSE + 256 + m * 16 + p];
        float mx = logit;
        #pragma unroll
        for (int o = 8; o >= 1; o >>= 1)
            mx = fmaxf(mx, __shfl_xor_sync(0xffffffffu, mx, o, 16));
        float e = __expf(logit - mx);
        float s = e;
        #pragma unroll
        for (int o = 8; o >= 1; o >>= 1)
            s += __shfl_xor_sync(0xffffffffu, s, o, 16);
        float prob = e / s;

        float2 offv = *reinterpret_cast<const float2*>(
            g_oa + (size_t)nq * NFUSE + m * 32 + 2 * p);
        float2 refv = *reinterpret_cast<const float2*>(
            refpts + (size_t)nq * 8 + 2 * l);

        const int Wi = c_W[l], Hi = c_H[l];
        const float Wf = (float)Wi, Hf = (float)Hi;

        float x = fmaf(refv.x, Wf, offv.x) - 0.5f;
        float y = fmaf(refv.y, Hf, offv.y) - 0.5f;
        float x0f = floorf(x), y0f = floorf(y);
        float wx = x - x0f, wy = y - y0f;
        int x0 = (int)x0f, y0 = (int)y0f;
        int x1 = x0 + 1;
        int yi = y0 + half;

        float vx0 = (x0 >= 0 && x0 < Wi) ? 1.f : 0.f;
        float vx1 = (x1 >= 0 && x1 < Wi) ? 1.f : 0.f;
        float vy  = (yi >= 0 && yi < Hi) ? 1.f : 0.f;
        float wyv = half ? wy : (1.f - wy);

        int cx0 = min(max(x0, 0), Wi - 1);
        int cx1 = min(max(x1, 0), Wi - 1);
        int cyi = min(max(yi, 0), Hi - 1);

        int rbase = (c_start[l] + cyi * Wi) * 8;    // uint2 units
        int o0 = rbase + cx0 * 8;
        int o1 = rbase + cx1 * 8;

        float pv = prob * wyv * vy;
        float w0 = (1.f - wx) * pv * vx0;
        float w1 = wx * pv * vx1;

        float4 st = make_float4(w0, __int_as_float(o0),
                                w1, __int_as_float(o1));
        *reinterpret_cast<float4*>(&s_aw[m][p * 4 + half * 2]) = st;
    }
    __syncwarp();

    const int g  = lane >> 3;
    const int lg = lane & 7;
    const uint2* vbase = reinterpret_cast<const uint2*>(g_valueh) +
                         ((size_t)(n * 8 + m) * LEN_IN) * 8 + lg;

    float4 acc = make_float4(0.f, 0.f, 0.f, 0.f);
    #pragma unroll
    for (int i = 0; i < 16; i++) {
        float2 e = s_aw[m][i * 4 + g];
        uint2 u = __ldg(vbase + __float_as_int(e.y));
        float2 f0 = __half22float2(*reinterpret_cast<const __half2*>(&u.x));
        float2 f1 = __half22float2(*reinterpret_cast<const __half2*>(&u.y));
        acc.x = fmaf(f0.x, e.x, acc.x);
        acc.y = fmaf(f0.y, e.x, acc.y);
        acc.z = fmaf(f1.x, e.x, acc.z);
        acc.w = fmaf(f1.y, e.x, acc.w);
    }

    #pragma unroll
    for (int o = 8; o <= 16; o <<= 1) {
        acc.x += __shfl_xor_sync(0xffffffffu, acc.x, o);
        acc.y += __shfl_xor_sync(0xffffffffu, acc.y, o);
        acc.z += __shfl_xor_sync(0xffffffffu, acc.z, o);
        acc.w += __shfl_xor_sync(0xffffffffu, acc.w, o);
    }

    if (lane < 8) {
        uint2 o;
        o.x = pack_h2(acc.x, acc.y);
        o.y = pack_h2(acc.z, acc.w);
        reinterpret_cast<uint2*>(g_msh)[(size_t)nq * 64 + m * 8 + lg] = o;
    }
}

// ---------------- launch ----------------
extern "C" void kernel_launch(void* const* d_in, const int* in_sizes, int n_in,
                              void* d_out, int out_size)
{
    const float* query         = (const float*)d_in[0];
    const float* refpts        = (const float*)d_in[1];
    const float* input_flatten = (const float*)d_in[2];
    const float* Wv     = (const float*)d_in[5];
    const float* bv     = (const float*)d_in[6];
    const float* W_off  = (const float*)d_in[7];
    const float* b_off  = (const float*)d_in[8];
    const float* W_attn = (const float*)d_in[9];
    const float* b_attn = (const float*)d_in[10];
    const float* Wo     = (const float*)d_in[11];
    const float* bo     = (const float*)d_in[12];
    float* out = (float*)d_out;

    void *p_valueh, *p_oa, *p_msh, *p_Wvh, *p_Wfh, *p_Woh, *p_bf;
    cudaGetSymbolAddress(&p_valueh, g_valueh);
    cudaGetSymbolAddress(&p_oa,     g_oa);
    cudaGetSymbolAddress(&p_msh,    g_msh);
    cudaGetSymbolAddress(&p_Wvh,    g_Wvh);
    cudaGetSymbolAddress(&p_Wfh,    g_Wfh);
    cudaGetSymbolAddress(&p_Woh,    g_Woh);
    cudaGetSymbolAddress(&p_bf,     g_bf);

    dim3 blk(256);
    dim3 g256(256 / BN, (NROWS + BM - 1) / BM);   // (2, 416)
    dim3 g384(NFUSE / BN, (NROWS + BM - 1) / BM); // (3, 416)

    prep<<<(NFUSE * 128 + 255) / 256, 256>>>(Wv, W_off, W_attn, Wo,
                                             b_off, b_attn);
    gemm_f16<0, 1><<<g256, blk>>>(input_flatten, (const uint32_t*)p_Wvh,
                                  bv, p_valueh, NROWS, 256);
    gemm_f16<0, 0><<<g384, blk>>>(query, (const uint32_t*)p_Wfh,
                                  (const float*)p_bf, p_oa, NROWS, NFUSE);
    msda_sample<<<NROWS, 256>>>(refpts);
    gemm_f16<1, 0><<<g256, blk>>>(p_msh, (const uint32_t*)p_Woh,
                                  bo, out, NROWS, 256);
}

// round 12
// speedup vs baseline: 1.4306x; 1.0433x over previous
#include <cuda_runtime.h>
#include <cuda_fp16.h>
#include <math.h>
#include <stdint.h>

// ---------------- problem constants (static in reference) ----------------
#define NB 4
#define LQ 13294
#define LEN_IN 13294
#define CC 256
#define NROWS (NB * LQ)   // 53176
#define NFUSE 384

__device__ __constant__ int c_H[4]     = {100, 50, 25, 13};
__device__ __constant__ int c_W[4]     = {100, 50, 25, 13};
__device__ __constant__ int c_start[4] = {0, 10000, 12500, 13125};

// ---------------- scratch (device globals, no allocation) ----------------
__device__ uint32_t g_valueh[NROWS * 128];  // value, head-major fp16
__device__ float    g_oa[NROWS * NFUSE];    // fused [off|attn] logits fp32
__device__ uint32_t g_msh[NROWS * 128];     // sampled output fp16 k-pairs
__device__ uint32_t g_Wvh[CC * 128];        // weights n-major fp16 k-pairs
__device__ uint32_t g_Wfh[NFUSE * 128];
__device__ uint32_t g_Woh[CC * 128];
__device__ float    g_bf[NFUSE];

__device__ __forceinline__ uint32_t pack_h2(float lo, float hi) {
    uint32_t u;
    asm("cvt.rn.f16x2.f32 %0, %1, %2;" : "=r"(u) : "f"(hi), "f"(lo));
    return u;
}

// ---------------- prep: pack weights to fp16, n-major ----------------
__global__ void prep(const float* __restrict__ Wv,
                     const float* __restrict__ W_off,
                     const float* __restrict__ W_attn,
                     const float* __restrict__ Wo,
                     const float* __restrict__ b_off,
                     const float* __restrict__ b_attn)
{
    int i = blockIdx.x * 256 + threadIdx.x;
    if (i < CC * 128) {
        int n = i >> 7, k2 = i & 127;
        g_Wvh[i] = pack_h2(Wv[(2 * k2) * CC + n], Wv[(2 * k2 + 1) * CC + n]);
        g_Woh[i] = pack_h2(Wo[(2 * k2) * CC + n], Wo[(2 * k2 + 1) * CC + n]);
    }
    if (i < NFUSE * 128) {
        int n = i >> 7, k2 = i & 127;
        float lo = (n < 256) ? W_off[(2 * k2) * 256 + n]
                             : W_attn[(2 * k2) * 128 + (n - 256)];
        float hi = (n < 256) ? W_off[(2 * k2 + 1) * 256 + n]
                             : W_attn[(2 * k2 + 1) * 128 + (n - 256)];
        g_Wfh[i] = pack_h2(lo, hi);
    }
    if (i < NFUSE) g_bf[i] = (i < 256) ? b_off[i] : b_attn[i - 256];
}

// ---------------- fp16 tensor-core GEMM, 3-stage cp.async pipeline --------
#define BM 128
#define BN 128
#define BK 32
#define PSTR 20                       // u32 row stride (16 payload + 4 pad)
#define A_ST (BM * PSTR)              // 2560 u32 per A stage
#define STAGE_U32 (2 * A_ST)          // A + B per stage
#define STAGE_B (STAGE_U32 * 4)       // 20480 bytes
#define SMEM_BYTES (3 * STAGE_B)      // 61440

__device__ __forceinline__ void mma_f16(float* d, const uint32_t* a,
                                        uint32_t b0, uint32_t b1) {
    asm volatile(
        "mma.sync.aligned.m16n8k16.row.col.f32.f16.f16.f32 "
        "{%0,%1,%2,%3},{%4,%5,%6,%7},{%8,%9},{%0,%1,%2,%3};"
        : "+f"(d[0]), "+f"(d[1]), "+f"(d[2]), "+f"(d[3])
        : "r"(a[0]), "r"(a[1]), "r"(a[2]), "r"(a[3]), "r"(b0), "r"(b1));
}

__device__ __forceinline__ void ldsm_x4(uint32_t* r, uint32_t addr) {
    asm volatile("ldmatrix.sync.aligned.m8n8.x4.shared.b16 {%0,%1,%2,%3}, [%4];"
        : "=r"(r[0]), "=r"(r[1]), "=r"(r[2]), "=r"(r[3]) : "r"(addr));
}

__device__ __forceinline__ void cp16(uint32_t smem_dst, const void* gsrc) {
    asm volatile("cp.async.cg.shared.global [%0], [%1], 16;"
                 :: "r"(smem_dst), "l"(gsrc) : "memory");
}
#define CP_COMMIT() asm volatile("cp.async.commit_group;" ::: "memory")

// AMODE: 0 = A fp32 row-major [Mrows][256]; 1 = A fp16 k-pair packed
// CMODE: 0 = C fp32 row-major; 1 = C fp16 head-major value layout
template <int AMODE, int CMODE>
__global__ __launch_bounds__(256, 2) void gemm_f16(
    const void* __restrict__ Ap, const uint32_t* __restrict__ Bh,
    const float* __restrict__ bias, void* __restrict__ Cp,
    int Mrows, int Ncols)
{
    extern __shared__ uint32_t sm[];
    const uint32_t smem_base = (uint32_t)__cvta_generic_to_shared(sm);

    const float*    A32 = (const float*)Ap;
    const uint32_t* A16 = (const uint32_t*)Ap;

    const int tid  = threadIdx.x;
    const int lane = tid & 31;
    const int wid  = tid >> 5;
    const int wm   = (wid & 3) * 32;
    const int wn   = (wid >> 2) * 64;
    const int row0 = blockIdx.y * BM;
    const int col0 = blockIdx.x * BN;
    const int r = lane >> 2;
    const int c = lane & 3;

    // ldmatrix per-lane in-stage byte offsets
    uint32_t a_rel[2], b_rel[4];
    {
        int arow = ((lane >> 3) & 1) * 8 + (lane & 7);
        int achk = (lane >> 4) * 16;
        #pragma unroll
        for (int mt = 0; mt < 2; mt++)
            a_rel[mt] = (wm + mt * 16 + arow) * (PSTR * 4) + achk;
        int brow = (lane >> 4) * 8 + (lane & 7);
        int bchk = ((lane >> 3) & 1) * 16;
        #pragma unroll
        for (int ntp = 0; ntp < 4; ntp++)
            b_rel[ntp] = A_ST * 4 + (wn + ntp * 16 + brow) * (PSTR * 4) + bchk;
    }

    // B fill mapping: 2 x 16B per thread
    int b_n[2], b_jj[2];
    #pragma unroll
    for (int j = 0; j < 2; j++) {
        int idx = tid + 256 * j;
        b_n[j]  = idx >> 2;
        b_jj[j] = idx & 3;
    }
    // A fill mappings
    int a_m4[4], a_kf[4];  bool a_ok4[4];   // AMODE 0
    int a_m2[2], a_kp[2];  bool a_ok2[2];   // AMODE 1
    if (AMODE == 0) {
        #pragma unroll
        for (int j = 0; j < 4; j++) {
            int idx = tid + 256 * j;
            a_m4[j]  = idx >> 3;
            a_kf[j]  = (idx & 7) << 2;
            a_ok4[j] = (row0 + a_m4[j]) < Mrows;
        }
    } else {
        #pragma unroll
        for (int j = 0; j < 2; j++) {
            int idx = tid + 256 * j;
            a_m2[j]  = idx >> 2;
            a_kp[j]  = (idx & 3) << 2;
            a_ok2[j] = (row0 + a_m2[j]) < Mrows;
        }
    }

    float acc[2][8][4];
    #pragma unroll
    for (int mt = 0; mt < 2; mt++)
        #pragma unroll
        for (int nt = 0; nt < 8; nt++)
            #pragma unroll
            for (int i = 0; i < 4; i++) acc[mt][nt][i] = 0.f;

    float4 ra[4];

    // ---- fill helpers (inlined logic) ----
    // A fp32 gload for tile t -> ra
    auto gloadA = [&](int t) {
        const int k0 = t * BK;
        #pragma unroll
        for (int j = 0; j < 4; j++)
            ra[j] = a_ok4[j] ? *reinterpret_cast<const float4*>(
                        A32 + (size_t)(row0 + a_m4[j]) * CC + k0 + a_kf[j])
                             : make_float4(0.f, 0.f, 0.f, 0.f);
    };
    // STS ra -> stage s
    auto stsA = [&](int s) {
        uint32_t* As = sm + s * STAGE_U32;
        #pragma unroll
        for (int j = 0; j < 4; j++) {
            uint2 u;
            u.x = pack_h2(ra[j].x, ra[j].y);
            u.y = pack_h2(ra[j].z, ra[j].w);
            *reinterpret_cast<uint2*>(&As[a_m4[j] * PSTR + (a_kf[j] >> 1)]) = u;
        }
    };
    // cp.async A (fp16) for tile t -> stage s
    auto cpA = [&](int t, int s) {
        const int kp0 = t * (BK / 2);
        #pragma unroll
        for (int j = 0; j < 2; j++)
            if (a_ok2[j])
                cp16(smem_base + s * STAGE_B + (a_m2[j] * PSTR + a_kp[j]) * 4,
                     A16 + (size_t)(row0 + a_m2[j]) * 128 + kp0 + a_kp[j]);
    };
    // cp.async B for tile t -> stage s
    auto cpB = [&](int t, int s) {
        const int kp0 = t * (BK / 2);
        #pragma unroll
        for (int j = 0; j < 2; j++)
            cp16(smem_base + s * STAGE_B + (A_ST + b_n[j] * PSTR + b_jj[j] * 4) * 4,
                 Bh + (size_t)(col0 + b_n[j]) * 128 + kp0 + b_jj[j] * 4);
    };

    // ---- prologue: stages 0,1 in flight, A tile2 in regs ----
    if (AMODE == 0) { gloadA(0); stsA(0); } else { cpA(0, 0); }
    cpB(0, 0);
    CP_COMMIT();
    if (AMODE == 0) { gloadA(1); stsA(1); } else { cpA(1, 1); }
    cpB(1, 1);
    CP_COMMIT();
    if (AMODE == 0) gloadA(2);

    #pragma unroll
    for (int kt = 0; kt < 8; kt++) {
        if (kt < 7) asm volatile("cp.async.wait_group 1;" ::: "memory");
        else        asm volatile("cp.async.wait_group 0;" ::: "memory");
        __syncthreads();

        const uint32_t stage_off = smem_base + (kt % 3) * STAGE_B;

        // fills for tile kt+2 (stage read at kt-1; safe after the sync above)
        if (kt <= 5) {
            const int nxt = (kt + 2) % 3;
            if (AMODE == 0) stsA(nxt);
            else            cpA(kt + 2, nxt);
            cpB(kt + 2, nxt);
            CP_COMMIT();
            if (AMODE == 0 && kt <= 4) gloadA(kt + 3);
        }

        // compute on stage kt%3
        #pragma unroll
        for (int ks = 0; ks < 2; ks++) {
            const uint32_t koff = ks * 32;
            uint32_t afr[2][4];
            ldsm_x4(afr[0], stage_off + a_rel[0] + koff);
            ldsm_x4(afr[1], stage_off + a_rel[1] + koff);
            #pragma unroll
            for (int ntp = 0; ntp < 4; ntp++) {
                uint32_t bfr[4];
                ldsm_x4(bfr, stage_off + b_rel[ntp] + koff);
                mma_f16(acc[0][2 * ntp + 0], afr[0], bfr[0], bfr[1]);
                mma_f16(acc[1][2 * ntp + 0], afr[1], bfr[0], bfr[1]);
                mma_f16(acc[0][2 * ntp + 1], afr[0], bfr[2], bfr[3]);
                mma_f16(acc[1][2 * ntp + 1], afr[1], bfr[2], bfr[3]);
            }
        }
    }

    // ---- epilogue ----
    const int c2 = c * 2;
    if (CMODE == 0) {
        float* C32 = (float*)Cp;
        #pragma unroll
        for (int mt = 0; mt < 2; mt++) {
            int row = row0 + wm + mt * 16 + r;
            #pragma unroll
            for (int nt = 0; nt < 8; nt++) {
                int col = col0 + wn + nt * 8 + c2;
                float b0 = __ldg(bias + col);
                float b1 = __ldg(bias + col + 1);
                if (row < Mrows) {
                    float2 v = make_float2(acc[mt][nt][0] + b0, acc[mt][nt][1] + b1);
                    *reinterpret_cast<float2*>(C32 + (size_t)row * Ncols + col) = v;
                }
                if (row + 8 < Mrows) {
                    float2 v = make_float2(acc[mt][nt][2] + b0, acc[mt][nt][3] + b1);
                    *reinterpret_cast<float2*>(C32 + (size_t)(row + 8) * Ncols + col) = v;
                }
            }
        }
    } else {
        uint32_t* C16 = (uint32_t*)Cp;
        #pragma unroll
        for (int mt = 0; mt < 2; mt++) {
            #pragma unroll
            for (int half = 0; half < 2; half++) {
                int row = row0 + wm + mt * 16 + r + half * 8;
                if (row >= Mrows) continue;
                int nb = row / LQ;
                int sp = row - nb * LQ;
                size_t base = ((size_t)(nb * 8) * LEN_IN + sp) * 16;
                #pragma unroll
                for (int nt = 0; nt < 8; nt++) {
                    int col = col0 + wn + nt * 8 + c2;
                    int head = col >> 5, ch = col & 31;
                    float v0 = acc[mt][nt][half * 2 + 0] + __ldg(bias + col);
                    float v1 = acc[mt][nt][half * 2 + 1] + __ldg(bias + col + 1);
                    C16[base + (size_t)head * (LEN_IN * 16) + (ch >> 1)] =
                        pack_h2(v0, v1);
                }
            }
        }
    }
}

// ---------------- sampling: one warp per (n, q, m) ----------------
__global__ __launch_bounds__(256) void msda_sample(const float* __restrict__ refpts)
{
    __shared__ float2 s_aw[8][64];

    const int nq = blockIdx.x;
    const int m = threadIdx.x >> 5;
    const int lane = threadIdx.x & 31;
    const int n = nq / LQ;

    {
        const int p = lane & 15;
        const int l = p >> 2;
        const int half = lane >> 4;

        float logit = g_oa[(size_t)nq * NFUSE + 256 + m * 16 + p];
        float mx = logit;
        #pragma unroll
        for (int o = 8; o >= 1; o >>= 1)
            mx = fmaxf(mx, __shfl_xor_sync(0xffffffffu, mx, o, 16));
        float e = __expf(logit - mx);
        float s = e;
        #pragma unroll
        for (int o = 8; o >= 1; o >>= 1)
            s += __shfl_xor_sync(0xffffffffu, s, o, 16);
        float prob = e / s;

        float2 offv = *reinterpret_cast<const float2*>(
            g_oa + (size_t)nq * NFUSE + m * 32 + 2 * p);
        float2 refv = *reinterpret_cast<const float2*>(
            refpts + (size_t)nq * 8 + 2 * l);

        const int Wi = c_W[l], Hi = c_H[l];
        const float Wf = (float)Wi, Hf = (float)Hi;

        float x = fmaf(refv.x, Wf, offv.x) - 0.5f;
        float y = fmaf(refv.y, Hf, offv.y) - 0.5f;
        float x0f = floorf(x), y0f = floorf(y);
        float wx = x - x0f, wy = y - y0f;
        int x0 = (int)x0f, y0 = (int)y0f;
        int x1 = x0 + 1;
        int yi = y0 + half;

        float vx0 = (x0 >= 0 && x0 < Wi) ? 1.f : 0.f;
        float vx1 = (x1 >= 0 && x1 < Wi) ? 1.f : 0.f;
        float vy  = (yi >= 0 && yi < Hi) ? 1.f : 0.f;
        float wyv = half ? wy : (1.f - wy);

        int cx0 = min(max(x0, 0), Wi - 1);
        int cx1 = min(max(x1, 0), Wi - 1);
        int cyi = min(max(yi, 0), Hi - 1);

        int rbase = (c_start[l] + cyi * Wi) * 8;    // uint2 units
        int o0 = rbase + cx0 * 8;
        int o1 = rbase + cx1 * 8;

        float pv = prob * wyv * vy;
        float w0 = (1.f - wx) * pv * vx0;
        float w1 = wx * pv * vx1;

        float4 st = make_float4(w0, __int_as_float(o0),
                                w1, __int_as_float(o1));
        *reinterpret_cast<float4*>(&s_aw[m][p * 4 + half * 2]) = st;
    }
    __syncwarp();

    const int g  = lane >> 3;
    const int lg = lane & 7;
    const uint2* vbase = reinterpret_cast<const uint2*>(g_valueh) +
                         ((size_t)(n * 8 + m) * LEN_IN) * 8 + lg;

    float4 acc = make_float4(0.f, 0.f, 0.f, 0.f);
    #pragma unroll
    for (int i = 0; i < 16; i++) {
        float2 e = s_aw[m][i * 4 + g];
        uint2 u = __ldg(vbase + __float_as_int(e.y));
        float2 f0 = __half22float2(*reinterpret_cast<const __half2*>(&u.x));
        float2 f1 = __half22float2(*reinterpret_cast<const __half2*>(&u.y));
        acc.x = fmaf(f0.x, e.x, acc.x);
        acc.y = fmaf(f0.y, e.x, acc.y);
        acc.z = fmaf(f1.x, e.x, acc.z);
        acc.w = fmaf(f1.y, e.x, acc.w);
    }

    #pragma unroll
    for (int o = 8; o <= 16; o <<= 1) {
        acc.x += __shfl_xor_sync(0xffffffffu, acc.x, o);
        acc.y += __shfl_xor_sync(0xffffffffu, acc.y, o);
        acc.z += __shfl_xor_sync(0xffffffffu, acc.z, o);
        acc.w += __shfl_xor_sync(0xffffffffu, acc.w, o);
    }

    if (lane < 8) {
        uint2 o;
        o.x = pack_h2(acc.x, acc.y);
        o.y = pack_h2(acc.z, acc.w);
        reinterpret_cast<uint2*>(g_msh)[(size_t)nq * 64 + m * 8 + lg] = o;
    }
}

// ---------------- launch ----------------
extern "C" void kernel_launch(void* const* d_in, const int* in_sizes, int n_in,
                              void* d_out, int out_size)
{
    const float* query         = (const float*)d_in[0];
    const float* refpts        = (const float*)d_in[1];
    const float* input_flatten = (const float*)d_in[2];
    const float* Wv     = (const float*)d_in[5];
    const float* bv     = (const float*)d_in[6];
    const float* W_off  = (const float*)d_in[7];
    const float* b_off  = (const float*)d_in[8];
    const float* W_attn = (const float*)d_in[9];
    const float* b_attn = (const float*)d_in[10];
    const float* Wo     = (const float*)d_in[11];
    const float* bo     = (const float*)d_in[12];
    float* out = (float*)d_out;

    void *p_valueh, *p_oa, *p_msh, *p_Wvh, *p_Wfh, *p_Woh, *p_bf;
    cudaGetSymbolAddress(&p_valueh, g_valueh);
    cudaGetSymbolAddress(&p_oa,     g_oa);
    cudaGetSymbolAddress(&p_msh,    g_msh);
    cudaGetSymbolAddress(&p_Wvh,    g_Wvh);
    cudaGetSymbolAddress(&p_Wfh,    g_Wfh);
    cudaGetSymbolAddress(&p_Woh,    g_Woh);
    cudaGetSymbolAddress(&p_bf,     g_bf);

    static int smem_set = 0;
    if (!smem_set) {
        cudaFuncSetAttribute(gemm_f16<0, 1>,
            cudaFuncAttributeMaxDynamicSharedMemorySize, SMEM_BYTES);
        cudaFuncSetAttribute(gemm_f16<0, 0>,
            cudaFuncAttributeMaxDynamicSharedMemorySize, SMEM_BYTES);
        cudaFuncSetAttribute(gemm_f16<1, 0>,
            cudaFuncAttributeMaxDynamicSharedMemorySize, SMEM_BYTES);
        smem_set = 1;
    }

    dim3 blk(256);
    dim3 g256(256 / BN, (NROWS + BM - 1) / BM);   // (2, 416)
    dim3 g384(NFUSE / BN, (NROWS + BM - 1) / BM); // (3, 416)

    prep<<<(NFUSE * 128 + 255) / 256, 256>>>(Wv, W_off, W_attn, Wo,
                                             b_off, b_attn);
    gemm_f16<0, 1><<<g256, blk, SMEM_BYTES>>>(input_flatten,
        (const uint32_t*)p_Wvh, bv, p_valueh, NROWS, 256);
    gemm_f16<0, 0><<<g384, blk, SMEM_BYTES>>>(query,
        (const uint32_t*)p_Wfh, (const float*)p_bf, p_oa, NROWS, NFUSE);
    msda_sample<<<NROWS, 256>>>(refpts);
    gemm_f16<1, 0><<<g256, blk, SMEM_BYTES>>>(p_msh,
        (const uint32_t*)p_Woh, bo, out, NROWS, 256);
}